// round 10
// baseline (speedup 1.0000x reference)
#include <cuda_runtime.h>
#include <cuda_fp16.h>

// ---------------------------------------------------------------------------
// KNNGaussianBlur: out = GaussianBlur_sigma4_radius12(img[0]) with replicate
// padding. (/max ... *max cancels -> no reduction.)
//
// R10: two-pass, fp16 scratch. vblur reverted to VROWS=16 (R9's VROWS=24
// regressed: register pressure beat traffic saving -> vblur is DRAM-latency/
// occupancy bound, not L2-amp bound). New: vblur threads own FLOAT2 columns
// -> accumulators 64->32 regs -> ~2x CTAs/SM -> ~40 warps/SM of in-flight
// LDGs to saturate HBM. Same bytes, same coalescing, same FFMA count.
// hblur unchanged (issue-bound at its 25-FFMA/px floor, 57.3us).
// ---------------------------------------------------------------------------

#define H_IMG 4096
#define W_IMG 4096
#define C_IMG 3
#define RADIUS 12

// 100.7 MB fp16 scratch (device global: allocation in kernel_launch is banned).
__device__ __half g_scratch[(size_t)C_IMG * H_IMG * W_IMG];

// 13 unique weights, compile-time constants -> FFMA-imm (rt_SMSP=1).
__device__ constexpr float KW[13] = {
    0.09990835f, 0.09683452f, 0.08816879f, 0.07541476f, 0.06059747f,
    0.04574137f, 0.03243549f, 0.02160670f, 0.01352113f, 0.00794866f,
    0.00438966f, 0.00227733f, 0.00110988f
};

// ------------------------------ Vertical pass ------------------------------
// Thread = one FLOAT2 column x 16 output rows; streams 40 input rows with
// row clamp (= replicate pad). Store converts to half2 (4B, coalesced).
constexpr int VROWS = 16;

__global__ __launch_bounds__(128)
void vblur_kernel(const float2* __restrict__ in) {
    const int W2 = W_IMG / 2;                      // 2048 f2-cols per row
    int col2 = blockIdx.x * 128 + threadIdx.x;     // 0..2047
    int y0   = blockIdx.y * VROWS;
    int cch  = blockIdx.z;

    const float2* inc  = in + (size_t)cch * ((size_t)H_IMG * W2);
    __half*       outc = g_scratch + (size_t)cch * ((size_t)H_IMG * W_IMG);

    float2 acc[VROWS];
#pragma unroll
    for (int i = 0; i < VROWS; ++i) acc[i] = make_float2(0.f, 0.f);

#pragma unroll
    for (int rr = 0; rr < VROWS + 2 * RADIUS; ++rr) {
        int row = y0 - RADIUS + rr;
        row = row < 0 ? 0 : (row > H_IMG - 1 ? H_IMG - 1 : row);
        float2 v = __ldg(&inc[(size_t)row * W2 + col2]);
#pragma unroll
        for (int i = 0; i < VROWS; ++i) {
            int d = rr - RADIUS - i;               // compile-time per (rr,i)
            if (d >= -RADIUS && d <= RADIUS) {
                float w = KW[d < 0 ? -d : d];
                acc[i].x = fmaf(v.x, w, acc[i].x);
                acc[i].y = fmaf(v.y, w, acc[i].y);
            }
        }
    }

#pragma unroll
    for (int i = 0; i < VROWS; ++i) {
        __half2 h = __floats2half2_rn(acc[i].x, acc[i].y);
        *(unsigned*)(outc + (size_t)(y0 + i) * W_IMG + 2 * (size_t)col2)
            = *(unsigned*)&h;
    }
}

// ----------------------------- Horizontal pass -----------------------------
// Unchanged from R8 (issue-bound at its 25-FFMA/px floor). Block = 256 thr =
// 8 warps = one row; lane owns a half8 slot (8 consecutive px); window = 5
// coalesced 16B loads; OOB slots broadcast the edge pixel (exact replicate
// padding since W = 4096 = 512*8). Streamed convert+FMA, fp32 accumulate.
__global__ __launch_bounds__(256)
void hblur_kernel(float* __restrict__ out) {
    int row  = blockIdx.x;
    int cch  = blockIdx.y;
    int w    = threadIdx.x >> 5;
    int lane = threadIdx.x & 31;

    size_t rbase = ((size_t)cch * H_IMG + row) * W_IMG;
    const __half* inr  = g_scratch + rbase;
    const uint4*  in16 = (const uint4*)inr;        // 512 slots of 8 halves

#pragma unroll
    for (int g = 0; g < 2; ++g) {
        int b8   = 64 * w + 32 * g + lane;         // owned slot 0..511
        int base = 8 * b8;                         // first output px

        float acc[8];
#pragma unroll
        for (int p = 0; p < 8; ++p) acc[p] = 0.f;

#pragma unroll
        for (int j = 0; j < 5; ++j) {
            int s = b8 - 2 + j;
            uint4 q;
            if (s >= 0 && s < W_IMG / 8) {
                q = __ldg(&in16[s]);
            } else {
                __half e = __ldg(&inr[s < 0 ? 0 : W_IMG - 1]);
                unsigned he = (unsigned)__half_as_ushort(e);
                he |= he << 16;
                q = make_uint4(he, he, he, he);
            }
#pragma unroll
            for (int h2i = 0; h2i < 4; ++h2i) {
                unsigned uq = (h2i == 0) ? q.x : (h2i == 1) ? q.y
                            : (h2i == 2) ? q.z : q.w;
                float2 f2 = __half22float2(*(__half2*)&uq);
#pragma unroll
                for (int k = 0; k < 2; ++k) {
                    int m  = 8 * j + 2 * h2i + k;  // 0..39, compile-time
                    float xv = k ? f2.y : f2.x;
#pragma unroll
                    for (int p = 0; p < 8; ++p) {
                        int d = m - 16 - p;        // compile-time tap offset
                        if (d >= -RADIUS && d <= RADIUS)
                            acc[p] = fmaf(xv, KW[d < 0 ? -d : d], acc[p]);
                    }
                }
            }
        }

        float* o = out + rbase + base;
        *(float4*)o       = make_float4(acc[0], acc[1], acc[2], acc[3]);
        *(float4*)(o + 4) = make_float4(acc[4], acc[5], acc[6], acc[7]);
    }
}

// ------------------------------ entry point --------------------------------
extern "C" void kernel_launch(void* const* d_in, const int* in_sizes, int n_in,
                              void* d_out, int out_size) {
    const float* img = (const float*)d_in[0];      // [1,3,4096,4096] fp32
    float* out = (float*)d_out;                    // [3,4096,4096] fp32

    dim3 vgrid(W_IMG / 2 / 128, H_IMG / VROWS, C_IMG);   // (16, 256, 3)
    vblur_kernel<<<vgrid, 128>>>((const float2*)img);

    dim3 hgrid(H_IMG, C_IMG);                            // (4096, 3)
    hblur_kernel<<<hgrid, 256>>>(out);
}

// round 11
// speedup vs baseline: 1.0377x; 1.0377x over previous
#include <cuda_runtime.h>
#include <cuda_fp16.h>

// ---------------------------------------------------------------------------
// KNNGaussianBlur: out = GaussianBlur_sigma4_radius12(img[0]) with replicate
// padding. (/max ... *max cancels -> no reduction.)
//
// R11: vblur restored to R8's best (float4 cols, VROWS=16, 61.6us ~ DRAM
// floor; R9 taller tiles and R10 float2 cols both regressed). hblur now
// processes TWO ROWS per thread with packed fma.rn.f32x2: both lanes share
// the SAME weight (13 u64 consts) and lane pairing is pack2(row0,row1) --
// register-pair allocation, not data shuffling. FFMA warp-instrs halve;
// issue-bound 57.8us -> DRAM/latency-bound ~46us.
// ---------------------------------------------------------------------------

#define H_IMG 4096
#define W_IMG 4096
#define C_IMG 3
#define RADIUS 12

// 100.7 MB fp16 scratch (device global: allocation in kernel_launch is banned).
__device__ __half g_scratch[(size_t)C_IMG * H_IMG * W_IMG];

// 13 unique weights, compile-time constants -> FFMA-imm in vblur.
__device__ constexpr float KW[13] = {
    0.09990835f, 0.09683452f, 0.08816879f, 0.07541476f, 0.06059747f,
    0.04574137f, 0.03243549f, 0.02160670f, 0.01352113f, 0.00794866f,
    0.00438966f, 0.00227733f, 0.00110988f
};

__device__ __forceinline__ unsigned long long pack2(float lo, float hi) {
    unsigned long long r;
    asm("mov.b64 %0, {%1, %2};" : "=l"(r) : "f"(lo), "f"(hi));
    return r;
}
__device__ __forceinline__ void unpack2(unsigned long long v, float& lo, float& hi) {
    asm("mov.b64 {%0, %1}, %2;" : "=f"(lo), "=f"(hi) : "l"(v));
}
__device__ __forceinline__ void fma2(unsigned long long& acc,
                                     unsigned long long a, unsigned long long w) {
    asm("fma.rn.f32x2 %0, %1, %2, %0;" : "+l"(acc) : "l"(a), "l"(w));
}

// ------------------------------ Vertical pass ------------------------------
// R8's proven best: thread = one f4 column x 16 output rows, 40-row stream,
// row clamp = replicate pad, half4 coalesced store. ~61.6us (DRAM floor).
constexpr int VROWS = 16;

__global__ __launch_bounds__(128)
void vblur_kernel(const float4* __restrict__ in) {
    const int W4 = W_IMG / 4;                      // 1024
    int col4 = blockIdx.x * 128 + threadIdx.x;     // 0..1023
    int y0   = blockIdx.y * VROWS;
    int cch  = blockIdx.z;

    const float4* inc  = in + (size_t)cch * ((size_t)H_IMG * W4);
    __half*       outc = g_scratch + (size_t)cch * ((size_t)H_IMG * W_IMG);

    float4 acc[VROWS];
#pragma unroll
    for (int i = 0; i < VROWS; ++i) acc[i] = make_float4(0.f, 0.f, 0.f, 0.f);

#pragma unroll
    for (int rr = 0; rr < VROWS + 2 * RADIUS; ++rr) {
        int row = y0 - RADIUS + rr;
        row = row < 0 ? 0 : (row > H_IMG - 1 ? H_IMG - 1 : row);
        float4 v = __ldg(&inc[(size_t)row * W4 + col4]);
#pragma unroll
        for (int i = 0; i < VROWS; ++i) {
            int d = rr - RADIUS - i;               // compile-time per (rr,i)
            if (d >= -RADIUS && d <= RADIUS) {
                float w = KW[d < 0 ? -d : d];
                acc[i].x = fmaf(v.x, w, acc[i].x);
                acc[i].y = fmaf(v.y, w, acc[i].y);
                acc[i].z = fmaf(v.z, w, acc[i].z);
                acc[i].w = fmaf(v.w, w, acc[i].w);
            }
        }
    }

#pragma unroll
    for (int i = 0; i < VROWS; ++i) {
        __half2 lo = __floats2half2_rn(acc[i].x, acc[i].y);
        __half2 hi = __floats2half2_rn(acc[i].z, acc[i].w);
        uint2 pk = make_uint2(*(unsigned*)&lo, *(unsigned*)&hi);
        *(uint2*)(outc + (size_t)(y0 + i) * W_IMG + 4 * (size_t)col4) = pk;
    }
}

// ----------------------------- Horizontal pass -----------------------------
// Block = 256 thr = 8 warps = one ROW-PAIR (rows 2*bx, 2*bx+1). Lane owns a
// half8 slot (8 consecutive px) in both rows; window = 5 coalesced 16B loads
// per row. Accumulators are f32x2 (lane0=row0, lane1=row1) so each fma.rn.
// f32x2 retires 2 FMAs with one shared weight. OOB slots broadcast the edge
// pixel (exact replicate padding since W = 4096 = 512*8).
__global__ __launch_bounds__(256)
void hblur_kernel(float* __restrict__ out) {
    int rp   = blockIdx.x;                         // row pair 0..2047
    int cch  = blockIdx.y;
    int w    = threadIdx.x >> 5;
    int lane = threadIdx.x & 31;

    size_t r0base = ((size_t)cch * H_IMG + 2 * rp) * W_IMG;
    const __half* inr0 = g_scratch + r0base;
    const __half* inr1 = inr0 + W_IMG;
    const uint4*  inA  = (const uint4*)inr0;       // 512 slots of 8 halves
    const uint4*  inB  = (const uint4*)inr1;

    // 13 shared weight-pair constants (w,w)
    unsigned long long w2[13];
#pragma unroll
    for (int k = 0; k < 13; ++k) w2[k] = pack2(KW[k], KW[k]);

#pragma unroll
    for (int g = 0; g < 2; ++g) {
        int b8   = 64 * w + 32 * g + lane;         // owned slot 0..511
        int base = 8 * b8;                         // first output px

        unsigned long long acc[8];
#pragma unroll
        for (int p = 0; p < 8; ++p) acc[p] = 0ull;

#pragma unroll
        for (int j = 0; j < 5; ++j) {
            int s = b8 - 2 + j;
            uint4 q0, q1;
            if (s >= 0 && s < W_IMG / 8) {
                q0 = __ldg(&inA[s]);
                q1 = __ldg(&inB[s]);
            } else {
                int ec = s < 0 ? 0 : W_IMG - 1;
                unsigned h0 = (unsigned)__half_as_ushort(__ldg(&inr0[ec]));
                unsigned h1 = (unsigned)__half_as_ushort(__ldg(&inr1[ec]));
                h0 |= h0 << 16;  h1 |= h1 << 16;
                q0 = make_uint4(h0, h0, h0, h0);
                q1 = make_uint4(h1, h1, h1, h1);
            }
#pragma unroll
            for (int h2i = 0; h2i < 4; ++h2i) {
                unsigned ua = (h2i == 0) ? q0.x : (h2i == 1) ? q0.y
                            : (h2i == 2) ? q0.z : q0.w;
                unsigned ub = (h2i == 0) ? q1.x : (h2i == 1) ? q1.y
                            : (h2i == 2) ? q1.z : q1.w;
                float2 fa = __half22float2(*(__half2*)&ua);   // row0: x, x+1
                float2 fb = __half22float2(*(__half2*)&ub);   // row1: x, x+1
#pragma unroll
                for (int k = 0; k < 2; ++k) {
                    int m = 8 * j + 2 * h2i + k;   // 0..39, compile-time
                    unsigned long long xv =
                        pack2(k ? fa.y : fa.x, k ? fb.y : fb.x);
#pragma unroll
                    for (int p = 0; p < 8; ++p) {
                        int d = m - 16 - p;        // compile-time tap offset
                        if (d >= -RADIUS && d <= RADIUS)
                            fma2(acc[p], xv, w2[d < 0 ? -d : d]);
                    }
                }
            }
        }

        float lo[8], hi[8];
#pragma unroll
        for (int p = 0; p < 8; ++p) unpack2(acc[p], lo[p], hi[p]);

        float* o0 = out + r0base + base;
        float* o1 = o0 + W_IMG;
        *(float4*)o0       = make_float4(lo[0], lo[1], lo[2], lo[3]);
        *(float4*)(o0 + 4) = make_float4(lo[4], lo[5], lo[6], lo[7]);
        *(float4*)o1       = make_float4(hi[0], hi[1], hi[2], hi[3]);
        *(float4*)(o1 + 4) = make_float4(hi[4], hi[5], hi[6], hi[7]);
    }
}

// ------------------------------ entry point --------------------------------
extern "C" void kernel_launch(void* const* d_in, const int* in_sizes, int n_in,
                              void* d_out, int out_size) {
    const float* img = (const float*)d_in[0];      // [1,3,4096,4096] fp32
    float* out = (float*)d_out;                    // [3,4096,4096] fp32

    dim3 vgrid(W_IMG / 4 / 128, H_IMG / VROWS, C_IMG);   // (8, 256, 3)
    vblur_kernel<<<vgrid, 128>>>((const float4*)img);

    dim3 hgrid(H_IMG / 2, C_IMG);                        // (2048, 3)
    hblur_kernel<<<hgrid, 256>>>(out);
}